// round 6
// baseline (speedup 1.0000x reference)
#include <cuda_runtime.h>
#include <cstdint>

#define BROWS 8192
#define KDIM  2048
#define NDIM  3072
#define NSUBJ 8

#define TM 128
#define TN 256
#define KC 32                      // K floats per stage
#define KITERS (KDIM/KC)           // 64
#define STAGES 4
#define NT_N (NDIM/TN)             // 12
#define MAXMT 72
#define NTHR 512                   // 16 warps: 2 (m) x 8 (n)

// ---- shared memory layout (bytes) ----
#define SM_ROWS 0                  // 128 ints (raw row list)
#define SM_BIAS 512                // 256 floats
#define SM_A    1536
#define A_ST    (TM*KC*4)          // 16384
#define SM_B    (SM_A + STAGES*A_ST)     // 67072
#define B_ROW   264                // 256 + 8 pad floats per k-row
#define B_ST    (KC*B_ROW*4)       // 33792
#define SMEM_BYTES (SM_B + STAGES*B_ST)  // 202240

// ---- device scratch ----
__device__ int g_rowlist[BROWS + NSUBJ*TM];
__device__ int g_tsubj[MAXMT];
__device__ int g_tbase[MAXMT];
__device__ int g_ntiles;

static __device__ __forceinline__ uint32_t smem_u32(const void* p) {
    uint32_t a;
    asm("{ .reg .u64 t; cvta.to.shared.u64 t, %1; cvt.u32.u64 %0, t; }"
        : "=r"(a) : "l"(p));
    return a;
}
#define CP16(dst, src) \
    asm volatile("cp.async.cg.shared.global [%0], [%1], 16;" :: "r"(dst), "l"(src))

static __device__ __forceinline__ uint32_t f2tf(float f) {
    uint32_t r;
    asm("cvt.rna.tf32.f32 %0, %1;" : "=r"(r) : "f"(f));
    return r;
}
static __device__ __forceinline__ void mma8(float* c, const uint32_t* a,
                                            const uint32_t* b) {
    asm volatile(
        "mma.sync.aligned.m16n8k8.row.col.f32.tf32.tf32.f32 "
        "{%0,%1,%2,%3}, {%4,%5,%6,%7}, {%8,%9}, {%0,%1,%2,%3};"
        : "+f"(c[0]), "+f"(c[1]), "+f"(c[2]), "+f"(c[3])
        : "r"(a[0]), "r"(a[1]), "r"(a[2]), "r"(a[3]), "r"(b[0]), "r"(b[1]));
}

// ---------- kernel 1: stable counting sort of rows by subject ----------
// subject_ids arrive as int32 (JAX x64-disabled).
__global__ void bucket_kernel(const int* __restrict__ sids) {
    __shared__ int cnt[256][NSUBJ];
    __shared__ int start[256][NSUBJ];
    __shared__ int tot[NSUBJ], offp[NSUBJ];
    int t = threadIdx.x;
    int loc[NSUBJ];
    int sv[32];
#pragma unroll
    for (int s = 0; s < NSUBJ; s++) loc[s] = 0;
    int base = t * 32;
#pragma unroll
    for (int i = 0; i < 32; i++) {
        int s = sids[base + i] & 7;
        sv[i] = s;
        loc[s]++;
    }
#pragma unroll
    for (int s = 0; s < NSUBJ; s++) cnt[t][s] = loc[s];
    __syncthreads();
    if (t < NSUBJ) {
        int a = 0;
        for (int u = 0; u < 256; u++) a += cnt[u][t];
        tot[t] = a;
    }
    __syncthreads();
    if (t == 0) {
        int off = 0, ntl = 0;
        for (int s = 0; s < NSUBJ; s++) {
            offp[s] = off;
            int c = tot[s];
            int ntiles = (c + TM - 1) / TM;
            for (int j = 0; j < ntiles; j++) {
                g_tsubj[ntl] = s;
                g_tbase[ntl] = off + j * TM;
                ntl++;
            }
            off += ntiles * TM;
        }
        g_ntiles = ntl;
    }
    __syncthreads();
    if (t < NSUBJ) {
        int s = t, run = offp[s];
        for (int u = 0; u < 256; u++) { start[u][s] = run; run += cnt[u][s]; }
        int c = tot[s];
        int pad = ((c + TM - 1) / TM) * TM;
        for (int j = c; j < pad; j++) g_rowlist[offp[s] + j] = -1;
    }
    __syncthreads();
    int p[NSUBJ];
#pragma unroll
    for (int s = 0; s < NSUBJ; s++) p[s] = start[t][s];
#pragma unroll
    for (int i = 0; i < 32; i++) {
        int s = sv[i];
        g_rowlist[p[s]++] = base + i;
    }
}

// ---------- kernel 2: tf32 mma.sync GEMM, gathered A, 16 warps ----------
__global__ void __launch_bounds__(NTHR, 1) gemm_kernel(
    const float* __restrict__ x, const float* __restrict__ w,
    const float* __restrict__ bias, float* __restrict__ out)
{
    const int mt = blockIdx.y;
    if (mt >= g_ntiles) return;
    extern __shared__ char smem[];
    int* rows = (int*)(smem + SM_ROWS);
    float* bsm = (float*)(smem + SM_BIAS);
    float* As = (float*)(smem + SM_A);
    float* Bs = (float*)(smem + SM_B);

    const int t = threadIdx.x;
    const int subj = g_tsubj[mt];
    const int rowbase = g_tbase[mt];
    const int n0 = blockIdx.x * TN;

    if (t < 128) rows[t] = g_rowlist[rowbase + t];
    if (t < 256) bsm[t] = bias[(size_t)subj * NDIM + n0 + t];
    __syncthreads();

    // ---- cp.async source/dest precompute (A only; B recomputed per call) ----
    const uint32_t sbA = smem_u32(As);
    const uint32_t sbB = smem_u32(Bs);
    const float* asrc[2];
    uint32_t adst[2];
#pragma unroll
    for (int j = 0; j < 2; j++) {
        int c = t + NTHR * j;              // 0..1023
        int row = c >> 3, k4 = c & 7;
        int rr = rows[row];
        if (rr < 0) rr = 0;
        asrc[j] = x + (size_t)rr * KDIM + k4 * 4;
        adst[j] = sbA + (uint32_t)(((k4 >> 1) * 1024 + (k4 & 1) * 512 + row * 4) * 4);
    }
    const float* wbase = w + (size_t)subj * KDIM * NDIM + n0;

    auto load_stage = [&](int ks, int slot) {
        uint32_t ao = (uint32_t)(slot * A_ST);
        int k0 = ks * KC;
#pragma unroll
        for (int j = 0; j < 2; j++) CP16(adst[j] + ao, asrc[j] + k0);
        uint32_t bo = (uint32_t)(slot * B_ST);
        const float* ws = wbase + (size_t)k0 * NDIM;
#pragma unroll
        for (int j = 0; j < 4; j++) {
            int c = t + NTHR * j;          // 0..2047
            int k = c >> 6, n4 = c & 63;
            CP16(sbB + bo + (uint32_t)((k * B_ROW + n4 * 4) * 4),
                 ws + (size_t)k * NDIM + n4 * 4);
        }
    };

    load_stage(0, 0); asm volatile("cp.async.commit_group;" ::: "memory");
    load_stage(1, 1); asm volatile("cp.async.commit_group;" ::: "memory");
    load_stage(2, 2); asm volatile("cp.async.commit_group;" ::: "memory");

    // ---- per-warp fragment setup: warp grid 2 (m) x 8 (n) ----
    const int wid = t >> 5, lane = t & 31;
    const int wm = wid & 1, wn = wid >> 1;      // wm: 64-row half, wn: 32-col slice
    const int gid = lane >> 2, tig = lane & 3;

    float acc[4][4][4];
#pragma unroll
    for (int m = 0; m < 4; m++)
#pragma unroll
        for (int n = 0; n < 4; n++)
#pragma unroll
            for (int i = 0; i < 4; i++) acc[m][n][i] = 0.0f;

    const int aBaseOff = wm * 256 + lane;               // float idx
    const int bBaseOff = tig * B_ROW + wn * 32 + gid;   // float idx

#pragma unroll 1
    for (int i = 0; i < KITERS; i++) {
        const int slot = i & 3;
        asm volatile("cp.async.wait_group 2;" ::: "memory");
        __syncthreads();
        // Refill ring slot (i+3)&3 == (i-1)&3: all warps finished it at i-1.
        if (i + 3 < KITERS) load_stage(i + 3, (i + 3) & 3);
        asm volatile("cp.async.commit_group;" ::: "memory");

        const float* Ast = As + slot * (A_ST / 4);
        const float* Bst = Bs + slot * (B_ST / 4);
#pragma unroll
        for (int kb = 0; kb < 4; kb++) {
            uint32_t a[4][4];
#pragma unroll
            for (int m = 0; m < 4; m++) {
                const float* p = Ast + kb * 1024 + aBaseOff + m * 64;
                a[m][0] = f2tf(p[0]);
                a[m][1] = f2tf(p[32]);
                a[m][2] = f2tf(p[512]);
                a[m][3] = f2tf(p[544]);
            }
            uint32_t b[4][2];
#pragma unroll
            for (int n = 0; n < 4; n++) {
                const float* p = Bst + kb * (8 * B_ROW) + bBaseOff + n * 8;
                b[n][0] = f2tf(p[0]);
                b[n][1] = f2tf(p[4 * B_ROW]);
            }
#pragma unroll
            for (int m = 0; m < 4; m++)
#pragma unroll
                for (int n = 0; n < 4; n++)
                    mma8(acc[m][n], a[m], b[n]);
        }
    }

    // ---- epilogue: add bias, scatter rows ----
#pragma unroll
    for (int m = 0; m < 4; m++) {
        int r0 = wm * 64 + m * 16 + gid;
        int ra = rows[r0], rb = rows[r0 + 8];
#pragma unroll
        for (int n = 0; n < 4; n++) {
            int lc = wn * 32 + n * 8 + tig * 2;
            float bv0 = bsm[lc], bv1 = bsm[lc + 1];
            if (ra >= 0) {
                float2 v = make_float2(acc[m][n][0] + bv0, acc[m][n][1] + bv1);
                *(float2*)(out + (size_t)ra * NDIM + n0 + lc) = v;
            }
            if (rb >= 0) {
                float2 v = make_float2(acc[m][n][2] + bv0, acc[m][n][3] + bv1);
                *(float2*)(out + (size_t)rb * NDIM + n0 + lc) = v;
            }
        }
    }
}

extern "C" void kernel_launch(void* const* d_in, const int* in_sizes, int n_in,
                              void* d_out, int out_size) {
    const float* x = (const float*)d_in[0];
    const int* sid = (const int*)d_in[1];
    const float* w = (const float*)d_in[2];
    const float* b = (const float*)d_in[3];
    float* out = (float*)d_out;

    cudaFuncSetAttribute(gemm_kernel,
                         cudaFuncAttributeMaxDynamicSharedMemorySize, SMEM_BYTES);
    bucket_kernel<<<1, 256>>>(sid);
    dim3 grid(NT_N, MAXMT);
    gemm_kernel<<<grid, NTHR, SMEM_BYTES>>>(x, w, b, out);
}

// round 7
// speedup vs baseline: 1.2725x; 1.2725x over previous
#include <cuda_runtime.h>
#include <cstdint>

#define BROWS 8192
#define KDIM  2048
#define NDIM  3072
#define NSUBJ 8

#define TM 128
#define TN 256
#define KC 32                      // K floats per stage
#define KITERS (KDIM/KC)           // 64
#define STAGES 4
#define NT_N (NDIM/TN)             // 12
#define MAXMT 72
#define NTHR 256                   // 8 warps: 2 (m) x 4 (n)

// ---- shared memory layout (bytes) ----
#define SM_ROWS 0                  // 128 ints (raw row list)
#define SM_BIAS 512                // 256 floats
#define SM_MBAR 1520               // 4 mbarriers * 8B (16B-aligned block start)
#define SM_A    1552               // 16B aligned
#define A_ST    (TM*KC*4)          // 16384
#define SM_B    (SM_A + STAGES*A_ST)     // 67088 (16B aligned)
#define B_ROW   264                // 256 + 8 pad floats per k-row (1056B = 66*16)
#define B_ST    (KC*B_ROW*4)       // 33792
#define SMEM_BYTES (SM_B + STAGES*B_ST)  // 202256
#define STAGE_BYTES (A_ST + KC*1024)     // 16384 + 32768 = 49152 tx bytes

// ---- device scratch ----
__device__ int g_rowlist[BROWS + NSUBJ*TM];
__device__ int g_tsubj[MAXMT];
__device__ int g_tbase[MAXMT];
__device__ int g_ntiles;
// Staged, gathered, pre-swizzled A: per (m-tile, k-stage) one contiguous 16KB
// block laid out exactly like the A SMEM stage. 72 * 64 * 4096 floats = 72MB.
__device__ float g_xstage[MAXMT * KITERS * (TM * KC)];

static __device__ __forceinline__ uint32_t smem_u32(const void* p) {
    uint32_t a;
    asm("{ .reg .u64 t; cvta.to.shared.u64 t, %1; cvt.u32.u64 %0, t; }"
        : "=r"(a) : "l"(p));
    return a;
}
static __device__ __forceinline__ uint32_t f2tf(float f) {
    uint32_t r;
    asm("cvt.rna.tf32.f32 %0, %1;" : "=r"(r) : "f"(f));
    return r;
}
static __device__ __forceinline__ void mma8(float* c, const uint32_t* a,
                                            const uint32_t* b) {
    asm volatile(
        "mma.sync.aligned.m16n8k8.row.col.f32.tf32.tf32.f32 "
        "{%0,%1,%2,%3}, {%4,%5,%6,%7}, {%8,%9}, {%0,%1,%2,%3};"
        : "+f"(c[0]), "+f"(c[1]), "+f"(c[2]), "+f"(c[3])
        : "r"(a[0]), "r"(a[1]), "r"(a[2]), "r"(a[3]), "r"(b[0]), "r"(b[1]));
}
static __device__ __forceinline__ void bulk_g2s(uint32_t dst, const void* src,
                                                uint32_t bytes, uint32_t mbar) {
    asm volatile(
        "cp.async.bulk.shared::cluster.global.mbarrier::complete_tx::bytes "
        "[%0], [%1], %2, [%3];"
        :: "r"(dst), "l"(src), "r"(bytes), "r"(mbar) : "memory");
}
#define MBARRIER_INIT(mb, cnt) \
    asm volatile("mbarrier.init.shared.b64 [%0], %1;" \
                 :: "r"((uint32_t)(mb)), "r"((uint32_t)(cnt)) : "memory")
#define MBARRIER_EXPECT_TX(mb, tx) \
    asm volatile("mbarrier.arrive.expect_tx.shared.b64 _, [%0], %1;" \
                 :: "r"((uint32_t)(mb)), "r"((uint32_t)(tx)) : "memory")
#define MBARRIER_WAIT_PARITY(mb, par) do {                                         \
    uint32_t _mb = (uint32_t)(mb), _pr = (uint32_t)(par), _dn;                     \
    asm volatile("{\n\t.reg .pred p;\n\t"                                          \
        "mbarrier.try_wait.parity.acquire.cta.shared::cta.b64 p, [%1], %2;\n\t"    \
        "selp.b32 %0, 1, 0, p;\n\t}"                                               \
        : "=r"(_dn) : "r"(_mb), "r"(_pr) : "memory");                              \
    if (!_dn) {                                                                    \
        asm volatile("{\n\t.reg .pred P1;\n\t"                                     \
        "WL_%=:\n\t"                                                               \
        "mbarrier.try_wait.parity.acquire.cta.shared::cta.b64 P1, [%0], %1, 0x989680;\n\t" \
        "@P1 bra.uni WD_%=;\n\t"                                                   \
        "bra.uni WL_%=;\n\t"                                                       \
        "WD_%=:\n\t}" :: "r"(_mb), "r"(_pr) : "memory");                           \
    }                                                                              \
} while (0)

// ---------- kernel 1: stable counting sort of rows by subject ----------
// subject_ids arrive as int32 (JAX x64-disabled).
__global__ void bucket_kernel(const int* __restrict__ sids) {
    __shared__ int cnt[256][NSUBJ];
    __shared__ int start[256][NSUBJ];
    __shared__ int tot[NSUBJ], offp[NSUBJ];
    int t = threadIdx.x;
    int loc[NSUBJ];
    int sv[32];
#pragma unroll
    for (int s = 0; s < NSUBJ; s++) loc[s] = 0;
    int base = t * 32;
#pragma unroll
    for (int i = 0; i < 32; i++) {
        int s = sids[base + i] & 7;
        sv[i] = s;
        loc[s]++;
    }
#pragma unroll
    for (int s = 0; s < NSUBJ; s++) cnt[t][s] = loc[s];
    __syncthreads();
    if (t < NSUBJ) {
        int a = 0;
        for (int u = 0; u < 256; u++) a += cnt[u][t];
        tot[t] = a;
    }
    __syncthreads();
    if (t == 0) {
        int off = 0, ntl = 0;
        for (int s = 0; s < NSUBJ; s++) {
            offp[s] = off;
            int c = tot[s];
            int ntiles = (c + TM - 1) / TM;
            for (int j = 0; j < ntiles; j++) {
                g_tsubj[ntl] = s;
                g_tbase[ntl] = off + j * TM;
                ntl++;
            }
            off += ntiles * TM;
        }
        g_ntiles = ntl;
    }
    __syncthreads();
    if (t < NSUBJ) {
        int s = t, run = offp[s];
        for (int u = 0; u < 256; u++) { start[u][s] = run; run += cnt[u][s]; }
        int c = tot[s];
        int pad = ((c + TM - 1) / TM) * TM;
        for (int j = c; j < pad; j++) g_rowlist[offp[s] + j] = -1;
    }
    __syncthreads();
    int p[NSUBJ];
#pragma unroll
    for (int s = 0; s < NSUBJ; s++) p[s] = start[t][s];
#pragma unroll
    for (int i = 0; i < 32; i++) {
        int s = sv[i];
        g_rowlist[p[s]++] = base + i;
    }
}

// ---------- kernel 1b: gather + pre-swizzle A into staging ----------
// Writes each (m-tile, k-stage) as one contiguous 16KB block in the exact
// interleaved layout the GEMM's A SMEM stage uses, so the GEMM can fetch it
// with a single cp.async.bulk.
__global__ void gather_kernel(const float* __restrict__ x) {
    const int mt = blockIdx.y;
    if (mt >= g_ntiles) return;
    const int ks = blockIdx.x;
    const int rowbase = g_tbase[mt];
    float* dst = g_xstage + (size_t)(mt * KITERS + ks) * (TM * KC);
    const int t = threadIdx.x;
#pragma unroll
    for (int q = 0; q < 4; q++) {
        int j = t + q * 256;               // 0..1023
        int row = j >> 3, k4 = j & 7;
        int r = g_rowlist[rowbase + row];
        if (r < 0) r = 0;
        float4 v = *(const float4*)(x + (size_t)r * KDIM + ks * KC + k4 * 4);
        int off = (k4 >> 1) * 1024 + (k4 & 1) * 512 + row * 4;
        *(float4*)(dst + off) = v;
    }
}

// ---------- kernel 2: tf32 mma.sync GEMM, bulk-async loads ----------
__global__ void __launch_bounds__(NTHR, 1) gemm_kernel(
    const float* __restrict__ w, const float* __restrict__ bias,
    float* __restrict__ out)
{
    const int mt = blockIdx.y;
    if (mt >= g_ntiles) return;
    extern __shared__ char smem[];
    int* rows = (int*)(smem + SM_ROWS);
    float* bsm = (float*)(smem + SM_BIAS);
    float* As = (float*)(smem + SM_A);
    float* Bs = (float*)(smem + SM_B);

    const int t = threadIdx.x;
    const int wid = t >> 5, lane = t & 31;
    const uint32_t sb = smem_u32(smem);
    const int subj = g_tsubj[mt];
    const int rowbase = g_tbase[mt];
    const int n0 = blockIdx.x * TN;

    if (t < 128) rows[t] = g_rowlist[rowbase + t];
    bsm[t] = bias[(size_t)subj * NDIM + n0 + t];
    if (t == 0) {
        for (int s = 0; s < STAGES; s++) MBARRIER_INIT(sb + SM_MBAR + s * 8, 1);
        asm volatile("fence.proxy.async.shared::cta;" ::: "memory");
    }
    __syncthreads();

    const float* wbase = w + (size_t)subj * KDIM * NDIM + n0;
    const float* astage = g_xstage + (size_t)mt * KITERS * (TM * KC);

    // warp 0 fills a stage: 1 bulk for A (16KB) + 32 bulks for B (1KB rows)
    auto bulk_fill = [&](int ks, int slot) {
        uint32_t mbar = sb + SM_MBAR + slot * 8;
        if (lane == 0) {
            MBARRIER_EXPECT_TX(mbar, STAGE_BYTES);
            bulk_g2s(sb + SM_A + slot * A_ST, astage + (size_t)ks * (TM * KC),
                     A_ST, mbar);
        }
        __syncwarp();
        bulk_g2s(sb + SM_B + slot * B_ST + lane * (B_ROW * 4),
                 wbase + (size_t)(ks * KC + lane) * NDIM, 1024, mbar);
    };

    if (wid == 0) {
        bulk_fill(0, 0);
        bulk_fill(1, 1);
        bulk_fill(2, 2);
    }

    // ---- per-warp fragment setup: warp grid 2 (m) x 4 (n) ----
    const int wm = wid & 1, wn = wid >> 1;
    const int gid = lane >> 2, tig = lane & 3;

    float acc[4][8][4];
#pragma unroll
    for (int m = 0; m < 4; m++)
#pragma unroll
        for (int n = 0; n < 8; n++)
#pragma unroll
            for (int i = 0; i < 4; i++) acc[m][n][i] = 0.0f;

    const int aBaseOff = wm * 256 + lane;               // float idx
    const int bBaseOff = tig * B_ROW + wn * 64 + gid;   // float idx

#pragma unroll 1
    for (int i = 0; i < KITERS; i++) {
        const int slot = i & 3;
        __syncthreads();   // all warps done reading slot (i-1)&3 == (i+3)&3
        if (i + 3 < KITERS && wid == 0) bulk_fill(i + 3, (i + 3) & 3);
        MBARRIER_WAIT_PARITY(sb + SM_MBAR + slot * 8, (i >> 2) & 1);

        const float* Ast = As + slot * (A_ST / 4);
        const float* Bst = Bs + slot * (B_ST / 4);
#pragma unroll
        for (int kb = 0; kb < 4; kb++) {
            uint32_t a[4][4];
#pragma unroll
            for (int m = 0; m < 4; m++) {
                const float* p = Ast + kb * 1024 + aBaseOff + m * 64;
                a[m][0] = f2tf(p[0]);
                a[m][1] = f2tf(p[32]);
                a[m][2] = f2tf(p[512]);
                a[m][3] = f2tf(p[544]);
            }
            uint32_t b[8][2];
#pragma unroll
            for (int n = 0; n < 8; n++) {
                const float* p = Bst + kb * (8 * B_ROW) + bBaseOff + n * 8;
                b[n][0] = f2tf(p[0]);
                b[n][1] = f2tf(p[4 * B_ROW]);
            }
#pragma unroll
            for (int m = 0; m < 4; m++)
#pragma unroll
                for (int n = 0; n < 8; n++)
                    mma8(acc[m][n], a[m], b[n]);
        }
    }

    // ---- epilogue: add bias, scatter rows ----
#pragma unroll
    for (int m = 0; m < 4; m++) {
        int r0 = wm * 64 + m * 16 + gid;
        int ra = rows[r0], rb = rows[r0 + 8];
#pragma unroll
        for (int n = 0; n < 8; n++) {
            int lc = wn * 64 + n * 8 + tig * 2;
            float bv0 = bsm[lc], bv1 = bsm[lc + 1];
            if (ra >= 0) {
                float2 v = make_float2(acc[m][n][0] + bv0, acc[m][n][1] + bv1);
                *(float2*)(out + (size_t)ra * NDIM + n0 + lc) = v;
            }
            if (rb >= 0) {
                float2 v = make_float2(acc[m][n][2] + bv0, acc[m][n][3] + bv1);
                *(float2*)(out + (size_t)rb * NDIM + n0 + lc) = v;
            }
        }
    }
}

extern "C" void kernel_launch(void* const* d_in, const int* in_sizes, int n_in,
                              void* d_out, int out_size) {
    const float* x = (const float*)d_in[0];
    const int* sid = (const int*)d_in[1];
    const float* w = (const float*)d_in[2];
    const float* b = (const float*)d_in[3];
    float* out = (float*)d_out;

    cudaFuncSetAttribute(gemm_kernel,
                         cudaFuncAttributeMaxDynamicSharedMemorySize, SMEM_BYTES);
    bucket_kernel<<<1, 256>>>(sid);
    dim3 ggrid(KITERS, MAXMT);
    gather_kernel<<<ggrid, 256>>>(x);
    dim3 grid(NT_N, MAXMT);
    gemm_kernel<<<grid, NTHR, SMEM_BYTES>>>(w, b, out);
}